// round 16
// baseline (speedup 1.0000x reference)
#include <cuda_runtime.h>
#include <cuda_bf16.h>
#include <cstdint>

#define BATCH   8192
#define IN_DIM  256
#define HID_DIM 16384
#define OUT_DIM 256
#define K_SEL   256
#define LIST_CAP 320
#define BAND_CAP 64
#define CAND_CAP 768
#define NT3      256
#define NCHUNKS  4
#define CHROWS   (BATCH / NCHUNKS)

// bf16x2 split GEMM (3 terms): K expanded 3x (hi*hi, hi*mid, mid*hi)
#define KTOT  768

// HMMA tile config (round-8 proven: 128x128, warp 64x32, 2 CTA/SM)
#define BM 128
#define BN 128
#define BK 32
#define NSTAGES 4
#define KITERS (KTOT / BK)
#define STAGE_BYTES (2 * BM * BK * 2)
#define GEMM_SMEM (NSTAGES * STAGE_BYTES)

typedef unsigned long long u64;

__device__ float         g_dec_wT[(size_t)HID_DIM * OUT_DIM];
__device__ __nv_bfloat16 g_xs[(size_t)BATCH  * KTOT];
__device__ __nv_bfloat16 g_ws[(size_t)HID_DIM * KTOT];
__device__ int           g_nsel[BATCH];
__device__ int           g_lj[(size_t)BATCH * LIST_CAP];
__device__ float         g_lv[(size_t)BATCH * LIST_CAP];

// ---------------------------------------------------------------------------
// PTX helpers (sm_80-level only; ptxas targets sm_103 with no 'a' features)
// ---------------------------------------------------------------------------
__device__ __forceinline__ uint32_t smem_u32(const void* p) {
    uint32_t a;
    asm("{ .reg .u64 t; cvta.to.shared.u64 t, %1; cvt.u32.u64 %0, t; }" : "=r"(a) : "l"(p));
    return a;
}
__device__ __forceinline__ void cp16(uint32_t dst, const void* src) {
    asm volatile("cp.async.cg.shared.global [%0], [%1], 16;" :: "r"(dst), "l"(src));
}
__device__ __forceinline__ void cp_commit() {
    asm volatile("cp.async.commit_group;" ::: "memory");
}
__device__ __forceinline__ void ldsm4(uint32_t& r0, uint32_t& r1, uint32_t& r2, uint32_t& r3,
                                      uint32_t addr) {
    asm volatile("ldmatrix.sync.aligned.m8n8.x4.shared.b16 {%0,%1,%2,%3}, [%4];"
                 : "=r"(r0), "=r"(r1), "=r"(r2), "=r"(r3) : "r"(addr));
}
__device__ __forceinline__ void mma16816(float* c, const uint32_t* a, const uint32_t* b) {
    asm volatile(
        "mma.sync.aligned.m16n8k16.row.col.f32.bf16.bf16.f32 "
        "{%0,%1,%2,%3}, {%4,%5,%6,%7}, {%8,%9}, {%0,%1,%2,%3};"
        : "+f"(c[0]), "+f"(c[1]), "+f"(c[2]), "+f"(c[3])
        : "r"(a[0]), "r"(a[1]), "r"(a[2]), "r"(a[3]), "r"(b[0]), "r"(b[1]));
}

// ---------------------------------------------------------------------------
// split fp32 -> 2x bf16 along expanded K (3-term product)
// ---------------------------------------------------------------------------
__global__ void split_x(const float* __restrict__ x)
{
    const int i = blockIdx.x * 256 + threadIdx.x;
    const int m = i >> 8, k = i & 255;
    const float v = x[i];
    const __nv_bfloat16 hi = __float2bfloat16(v);
    const float r1 = v - __bfloat162float(hi);
    const __nv_bfloat16 mid = __float2bfloat16(r1);
    __nv_bfloat16* dst = g_xs + (size_t)m * KTOT + k;
    dst[0] = hi; dst[256] = hi; dst[512] = mid;
}
__global__ void split_w(const float* __restrict__ w)
{
    const int i = blockIdx.x * 256 + threadIdx.x;
    const int n = i >> 8, k = i & 255;
    const float v = w[i];
    const __nv_bfloat16 hi = __float2bfloat16(v);
    const float r1 = v - __bfloat162float(hi);
    const __nv_bfloat16 mid = __float2bfloat16(r1);
    __nv_bfloat16* dst = g_ws + (size_t)n * KTOT + k;
    dst[0] = hi; dst[256] = mid; dst[512] = hi;
}

// ---------------------------------------------------------------------------
// HMMA bf16 GEMM (round-8 config), chunked over batch via mbase.
// ---------------------------------------------------------------------------
__device__ __forceinline__ uint32_t sw_off(int row, int gran) {
    return (uint32_t)(row * 64 + ((gran ^ ((row >> 1) & 3)) << 4));
}

__global__ __launch_bounds__(256, 2)
void gemm1_mma(const float* __restrict__ bias, float* __restrict__ h, int mbase)
{
    extern __shared__ __align__(1024) char smem[];
    const uint32_t sb = smem_u32(smem);
    const int tid = threadIdx.x;
    const int wid = tid >> 5;
    const int lane = tid & 31;
    const int m0 = mbase + blockIdx.x * BM;
    const int n0 = blockIdx.y * BN;

    const int warp_m = wid >> 2;
    const int warp_n = wid & 3;

    float acc[4][4][4];
#pragma unroll
    for (int i = 0; i < 4; i++)
#pragma unroll
        for (int j = 0; j < 4; j++)
#pragma unroll
            for (int q = 0; q < 4; q++) acc[i][j][q] = 0.0f;

    const int ar0 = (tid + 0)   >> 2, ag0 = (tid + 0)   & 3;
    const int ar1 = (tid + 256) >> 2, ag1 = (tid + 256) & 3;

    auto issue = [&](int c, int s) {
        const uint32_t abase = sb + s * STAGE_BYTES;
        const uint32_t bbase = abase + BM * BK * 2;
        const __nv_bfloat16* ax = g_xs + (size_t)m0 * KTOT + c * BK;
        const __nv_bfloat16* bx = g_ws + (size_t)n0 * KTOT + c * BK;
        cp16(abase + sw_off(ar0, ag0), ax + (size_t)ar0 * KTOT + ag0 * 8);
        cp16(abase + sw_off(ar1, ag1), ax + (size_t)ar1 * KTOT + ag1 * 8);
        cp16(bbase + sw_off(ar0, ag0), bx + (size_t)ar0 * KTOT + ag0 * 8);
        cp16(bbase + sw_off(ar1, ag1), bx + (size_t)ar1 * KTOT + ag1 * 8);
    };

    issue(0, 0); cp_commit();
    issue(1, 1); cp_commit();
    issue(2, 2); cp_commit();

    const int a_row_in = warp_m * 64 + (lane & 15);
    const int a_gsel   = (lane >> 4);
    const int b_row_in = warp_n * 32 + (lane & 7) + ((lane >> 4) << 3);
    const int b_gsel   = (lane >> 3) & 1;

    for (int c = 0; c < KITERS; c++) {
        asm volatile("cp.async.wait_group 2;" ::: "memory");
        __syncthreads();

        if (c + 3 < KITERS) issue(c + 3, (c + 3) & (NSTAGES - 1));
        cp_commit();

        const uint32_t abase = sb + (c & (NSTAGES - 1)) * STAGE_BYTES;
        const uint32_t bbase = abase + BM * BK * 2;

#pragma unroll
        for (int ks = 0; ks < 2; ks++) {
            uint32_t af[4][4];
            uint32_t bf[4][2];
#pragma unroll
            for (int ti = 0; ti < 4; ti++) {
                const int r = a_row_in + ti * 16;
                ldsm4(af[ti][0], af[ti][1], af[ti][2], af[ti][3],
                      abase + sw_off(r, ks * 2 + a_gsel));
            }
#pragma unroll
            for (int tjj = 0; tjj < 2; tjj++) {
                const int r = b_row_in + tjj * 16;
                uint32_t r0, r1, r2, r3;
                ldsm4(r0, r1, r2, r3, bbase + sw_off(r, ks * 2 + b_gsel));
                bf[tjj * 2 + 0][0] = r0; bf[tjj * 2 + 0][1] = r1;
                bf[tjj * 2 + 1][0] = r2; bf[tjj * 2 + 1][1] = r3;
            }
#pragma unroll
            for (int ti = 0; ti < 4; ti++)
#pragma unroll
                for (int tj = 0; tj < 4; tj++)
                    mma16816(acc[ti][tj], af[ti], bf[tj]);
        }
        __syncthreads();
    }

    __syncthreads();
    float* esm = (float*)smem + wid * (64 * 32);
#pragma unroll
    for (int ti = 0; ti < 4; ti++)
#pragma unroll
        for (int tj = 0; tj < 4; tj++) {
            const int r = ti * 16 + (lane >> 2);
            const int cc = tj * 8 + (lane & 3) * 2;
            esm[r * 32 + cc]            = acc[ti][tj][0];
            esm[r * 32 + cc + 1]        = acc[ti][tj][1];
            esm[(r + 8) * 32 + cc]      = acc[ti][tj][2];
            esm[(r + 8) * 32 + cc + 1]  = acc[ti][tj][3];
        }
    __syncwarp();
    {
        const int col = n0 + warp_n * 32 + lane;
        const float bl = bias[col];
        float* hb = h + (size_t)(m0 + warp_m * 64) * HID_DIM + col;
#pragma unroll 4
        for (int r = 0; r < 64; r++) {
            float v = esm[r * 32 + lane] + bl;
            hb[(size_t)r * HID_DIM] = v > 0.0f ? v : 0.0f;
        }
    }
}

// ---------------------------------------------------------------------------
// transpose dec_w
// ---------------------------------------------------------------------------
__global__ void transpose_dec(const float* __restrict__ dec_w)
{
    __shared__ float tile[32][33];
    const int j0 = blockIdx.x * 32;
    const int o0 = blockIdx.y * 32;
    const int tx = threadIdx.x;
    const int ty = threadIdx.y;
#pragma unroll
    for (int i = 0; i < 4; i++)
        tile[ty + i * 8][tx] = dec_w[(size_t)(o0 + ty + i * 8) * HID_DIM + (j0 + tx)];
    __syncthreads();
#pragma unroll
    for (int i = 0; i < 4; i++)
        g_dec_wT[(size_t)(j0 + ty + i * 8) * OUT_DIM + (o0 + tx)] = tile[tx][ty + i * 8];
}

// ---------------------------------------------------------------------------
// Kernel 3a: selection — byte-identical round-8 logic, chunked via rbase.
// ---------------------------------------------------------------------------
__global__ __launch_bounds__(NT3)
void topk_select(const float* __restrict__ x,
                 const float* __restrict__ enc_w,
                 const float* __restrict__ enc_b,
                 float* __restrict__ hidden,
                 int rbase)
{
    __shared__ unsigned hist[2048];
    __shared__ int scanbuf[NT3];
    __shared__ int cand_idx[CAND_CAP];
    __shared__ float cand_val[CAND_CAP];
    __shared__ float cand_out[CAND_CAP];
    __shared__ unsigned char cand_keep[CAND_CAP];
    __shared__ float xrow[IN_DIM];
    __shared__ int band_c[BAND_CAP];
    __shared__ float band_ex[BAND_CAP];
    __shared__ int wsum[8];
    __shared__ int s_pos, s_ccnt, s_bin, s_hidef, s_tbits, s_def, s_hi2, s_bandcnt, s_keepcnt;

    const int tid = threadIdx.x;
    const int lane = tid & 31, warp = tid >> 5;
    const int brow = rbase + blockIdx.x;
    float* hrow = hidden + (size_t)brow * HID_DIM;
    float4* hv = (float4*)hrow;

#pragma unroll
    for (int i = tid; i < 2048; i += NT3) hist[i] = 0u;
    xrow[tid] = x[(size_t)brow * IN_DIM + tid];
    if (tid == 0) { s_pos = 0; s_ccnt = 0; s_bin = -1; s_hidef = 0; s_tbits = 0;
                    s_hi2 = 0; s_bandcnt = 0; s_keepcnt = 0; }
    __syncthreads();

    // ---- Pass A: histogram of positive values (bins = u>>20) ----
    {
        int my_pos = 0;
        for (int i = tid; i < HID_DIM / 4; i += NT3) {
            const float4 v = hv[i];
            if (v.x > 0.0f) { my_pos++; atomicAdd(&hist[__float_as_uint(v.x) >> 20], 1u); }
            if (v.y > 0.0f) { my_pos++; atomicAdd(&hist[__float_as_uint(v.y) >> 20], 1u); }
            if (v.z > 0.0f) { my_pos++; atomicAdd(&hist[__float_as_uint(v.z) >> 20], 1u); }
            if (v.w > 0.0f) { my_pos++; atomicAdd(&hist[__float_as_uint(v.w) >> 20], 1u); }
        }
#pragma unroll
        for (int o = 16; o; o >>= 1) my_pos += __shfl_xor_sync(0xffffffffu, my_pos, o);
        if (lane == 0) atomicAdd(&s_pos, my_pos);
    }
    __syncthreads();

    if (s_pos < K_SEL) {
        if (tid == 0) g_nsel[brow] = -1;
        return;
    }

    const int b8 = tid * 8;
    {
        int ts = 0;
#pragma unroll
        for (int q = 0; q < 8; q++) ts += (int)hist[b8 + q];
        scanbuf[tid] = ts;
        __syncthreads();
        for (int off = 1; off < NT3; off <<= 1) {
            const int add = (tid + off < NT3) ? scanbuf[tid + off] : 0;
            __syncthreads();
            scanbuf[tid] += add;
            __syncthreads();
        }
        int running = (tid < NT3 - 1) ? scanbuf[tid + 1] : 0;
        for (int bb = b8 + 7; bb >= b8; bb--) {
            const int c = (int)hist[bb];
            if (running < K_SEL && running + c >= K_SEL) s_bin = bb;
            running += c;
        }
    }
    __syncthreads();
    const int b = s_bin;
    if (b <= 8) {
        if (tid == 0) g_nsel[brow] = -1;
        return;
    }
    {
        int part = 0;
#pragma unroll
        for (int q = 0; q < 8; q++) { const int bb = b8 + q; if (bb >= b + 2) part += (int)hist[bb]; }
#pragma unroll
        for (int o = 16; o; o >>= 1) part += __shfl_xor_sync(0xffffffffu, part, o);
        if (lane == 0) atomicAdd(&s_hidef, part);
    }
    __syncthreads();

    // ---- Pass B: write post (definite/zero) in place, collect candidates ----
    int cnt = 0;
    for (int i = tid; i < HID_DIM / 4; i += NT3) {
        float4 v = hv[i];
        float4 o;
        {
            const int ub = (int)(__float_as_uint(v.x) >> 20);
            if (v.x > 0.0f && ub >= b + 2) { o.x = v.x; cnt++; }
            else { o.x = 0.0f; if (v.x > 0.0f && ub >= b - 1 && ub <= b + 1) {
                const int p = atomicAdd(&s_ccnt, 1);
                if (p < CAND_CAP) { cand_idx[p] = i * 4 + 0; cand_val[p] = v.x; } } }
        }
        {
            const int ub = (int)(__float_as_uint(v.y) >> 20);
            if (v.y > 0.0f && ub >= b + 2) { o.y = v.y; cnt++; }
            else { o.y = 0.0f; if (v.y > 0.0f && ub >= b - 1 && ub <= b + 1) {
                const int p = atomicAdd(&s_ccnt, 1);
                if (p < CAND_CAP) { cand_idx[p] = i * 4 + 1; cand_val[p] = v.y; } } }
        }
        {
            const int ub = (int)(__float_as_uint(v.z) >> 20);
            if (v.z > 0.0f && ub >= b + 2) { o.z = v.z; cnt++; }
            else { o.z = 0.0f; if (v.z > 0.0f && ub >= b - 1 && ub <= b + 1) {
                const int p = atomicAdd(&s_ccnt, 1);
                if (p < CAND_CAP) { cand_idx[p] = i * 4 + 2; cand_val[p] = v.z; } } }
        }
        {
            const int ub = (int)(__float_as_uint(v.w) >> 20);
            if (v.w > 0.0f && ub >= b + 2) { o.w = v.w; cnt++; }
            else { o.w = 0.0f; if (v.w > 0.0f && ub >= b - 1 && ub <= b + 1) {
                const int p = atomicAdd(&s_ccnt, 1);
                if (p < CAND_CAP) { cand_idx[p] = i * 4 + 3; cand_val[p] = v.w; } } }
        }
        hv[i] = o;
    }
    __syncthreads();

    // ---- scan definite counts -> deterministic list bases ----
    int incl = cnt;
#pragma unroll
    for (int o = 1; o < 32; o <<= 1) {
        const int n = __shfl_up_sync(0xffffffffu, incl, o);
        if (lane >= o) incl += n;
    }
    if (lane == 31) wsum[warp] = incl;
    __syncthreads();
    if (warp == 0 && lane < 8) {
        int v = wsum[lane];
        int s = v;
#pragma unroll
        for (int o = 1; o < 8; o <<= 1) {
            const int n = __shfl_up_sync(0x000000ffu, s, o);
            if (lane >= o) s += n;
        }
        wsum[lane] = s - v;
        if (lane == 7) s_def = s;
    }
    __syncthreads();
    int base = wsum[warp] + (incl - cnt);

    for (int i = tid; i < HID_DIM / 4; i += NT3) {
        const float4 v = hv[i];
        if (v.x != 0.0f) {
            if (base < LIST_CAP) { g_lj[(size_t)brow * LIST_CAP + base] = i * 4 + 0;
                                   g_lv[(size_t)brow * LIST_CAP + base] = v.x; }
            base++;
        }
        if (v.y != 0.0f) {
            if (base < LIST_CAP) { g_lj[(size_t)brow * LIST_CAP + base] = i * 4 + 1;
                                   g_lv[(size_t)brow * LIST_CAP + base] = v.y; }
            base++;
        }
        if (v.z != 0.0f) {
            if (base < LIST_CAP) { g_lj[(size_t)brow * LIST_CAP + base] = i * 4 + 2;
                                   g_lv[(size_t)brow * LIST_CAP + base] = v.z; }
            base++;
        }
        if (v.w != 0.0f) {
            if (base < LIST_CAP) { g_lj[(size_t)brow * LIST_CAP + base] = i * 4 + 3;
                                   g_lv[(size_t)brow * LIST_CAP + base] = v.w; }
            base++;
        }
    }

    // ---- exact threshold among candidates ----
    const int C = (s_ccnt < CAND_CAP) ? s_ccnt : CAND_CAP;
    const int k_rem = K_SEL - s_hidef;
    for (int c = tid; c < C; c += NT3) {
        const float mine = cand_val[c];
        int gt = 0, eq = 0;
        for (int j = 0; j < C; j++) {
            const float o = cand_val[j];
            gt += (o > mine); eq += (o == mine);
        }
        if (gt < k_rem && gt + eq >= k_rem) s_tbits = __float_as_int(mine);
    }
    __syncthreads();
    const float t = __int_as_float(s_tbits);
    const float eps = 3e-3f;

    for (int c = tid; c < C; c += NT3) {
        const float v = cand_val[c];
        if (v > t + eps) { cand_keep[c] = 1; cand_out[c] = v; atomicAdd(&s_hi2, 1); }
        else if (v >= t - eps) {
            cand_keep[c] = 0;
            const int p = atomicAdd(&s_bandcnt, 1);
            if (p < BAND_CAP) band_c[p] = c;
        } else cand_keep[c] = 0;
    }
    __syncthreads();
    const int bc = (s_bandcnt < BAND_CAP) ? s_bandcnt : BAND_CAP;
    const int k_remb = k_rem - s_hi2;
    if (tid < bc) {
        const int j = cand_idx[band_c[tid]];
        const float4* wj = (const float4*)(enc_w + (size_t)j * IN_DIM);
        float acc = 0.0f;
#pragma unroll 8
        for (int k4 = 0; k4 < IN_DIM / 4; k4++) {
            const float4 wv = __ldg(&wj[k4]);
            acc = fmaf(xrow[k4 * 4 + 0], wv.x, acc);
            acc = fmaf(xrow[k4 * 4 + 1], wv.y, acc);
            acc = fmaf(xrow[k4 * 4 + 2], wv.z, acc);
            acc = fmaf(xrow[k4 * 4 + 3], wv.w, acc);
        }
        acc += enc_b[j];
        band_ex[tid] = acc > 0.0f ? acc : 0.0f;
    }
    __syncthreads();
    if (tid < bc) {
        const float mine = band_ex[tid];
        int gt = 0;
        for (int q = 0; q < bc; q++) gt += (band_ex[q] > mine);
        if (gt < k_remb) {
            const int c = band_c[tid];
            cand_keep[c] = 1;
            cand_out[c] = band_ex[tid];
        }
    }
    __syncthreads();

    for (int c = tid; c < C; c += NT3) {
        if (cand_keep[c]) {
            const int myidx = cand_idx[c];
            int pos = 0;
            for (int j = 0; j < C; j++)
                pos += (cand_keep[j] && cand_idx[j] < myidx);
            const int slot = s_def + pos;
            if (slot < LIST_CAP) {
                g_lj[(size_t)brow * LIST_CAP + slot] = myidx;
                g_lv[(size_t)brow * LIST_CAP + slot] = cand_out[c];
            }
            hrow[myidx] = cand_out[c];
            atomicAdd(&s_keepcnt, 1);
        }
    }
    __syncthreads();
    if (tid == 0) {
        int n = s_def + s_keepcnt;
        g_nsel[brow] = (n < LIST_CAP) ? n : LIST_CAP;
    }
}

// ---------------------------------------------------------------------------
// Kernel 3b: sparse decode GEMM (round-8 version), chunked via rbase
// ---------------------------------------------------------------------------
__global__ __launch_bounds__(256)
void gemm2_sparse(const float* __restrict__ dec_b,
                  const float* __restrict__ hidden,
                  float* __restrict__ out,
                  int rbase)
{
    __shared__ int lj[LIST_CAP];
    __shared__ float lv[LIST_CAP];
    const int tid = threadIdx.x;
    const int brow = rbase + blockIdx.x;
    const int nsel = g_nsel[brow];

    float acc = dec_b[tid];
    if (nsel >= 0) {
        for (int i = tid; i < nsel; i += 256) {
            lj[i] = g_lj[(size_t)brow * LIST_CAP + i];
            lv[i] = g_lv[(size_t)brow * LIST_CAP + i];
        }
        __syncthreads();
        int s = 0;
        for (; s + 4 <= nsel; s += 4) {
            acc = fmaf(lv[s + 0], g_dec_wT[(size_t)lj[s + 0] * OUT_DIM + tid], acc);
            acc = fmaf(lv[s + 1], g_dec_wT[(size_t)lj[s + 1] * OUT_DIM + tid], acc);
            acc = fmaf(lv[s + 2], g_dec_wT[(size_t)lj[s + 2] * OUT_DIM + tid], acc);
            acc = fmaf(lv[s + 3], g_dec_wT[(size_t)lj[s + 3] * OUT_DIM + tid], acc);
        }
        for (; s < nsel; s++)
            acc = fmaf(lv[s], g_dec_wT[(size_t)lj[s] * OUT_DIM + tid], acc);
    } else {
        const float* hrow = hidden + (size_t)brow * HID_DIM;
        for (int j = 0; j < HID_DIM; j++)
            acc = fmaf(__ldg(&hrow[j]), g_dec_wT[(size_t)j * OUT_DIM + tid], acc);
    }
    out[(size_t)brow * OUT_DIM + tid] = acc;
}

// ---------------------------------------------------------------------------
// Launch: 4-chunk pipeline, topk+gemm2 forked onto a side stream so they
// overlap the next gemm1 chunk. Capture-safe: only launches + event ops.
// ---------------------------------------------------------------------------
extern "C" void kernel_launch(void* const* d_in, const int* in_sizes, int n_in,
                              void* d_out, int out_size)
{
    const float* x     = (const float*)d_in[0];
    const float* enc_w = (const float*)d_in[1];
    const float* enc_b = (const float*)d_in[2];
    const float* dec_w = (const float*)d_in[3];
    const float* dec_b = (const float*)d_in[4];

    float* out    = (float*)d_out;
    float* hidden = (float*)d_out + (size_t)BATCH * OUT_DIM;

    cudaFuncSetAttribute(gemm1_mma,
                         cudaFuncAttributeMaxDynamicSharedMemorySize,
                         GEMM_SMEM);

    cudaStream_t sK;
    cudaStreamCreateWithFlags(&sK, cudaStreamNonBlocking);
    cudaEvent_t eG[NCHUNKS], eEnd;
    for (int c = 0; c < NCHUNKS; c++)
        cudaEventCreateWithFlags(&eG[c], cudaEventDisableTiming);
    cudaEventCreateWithFlags(&eEnd, cudaEventDisableTiming);

    // prep on main (legacy) stream
    {
        dim3 grid(HID_DIM / 32, OUT_DIM / 32);
        dim3 block(32, 8);
        transpose_dec<<<grid, block>>>(dec_w);
    }
    split_x<<<(BATCH * IN_DIM) / 256, 256>>>(x);
    split_w<<<((size_t)HID_DIM * IN_DIM) / 256, 256>>>(enc_w);

    for (int c = 0; c < NCHUNKS; c++) {
        const int mbase = c * CHROWS;
        dim3 grid(CHROWS / BM, HID_DIM / BN);
        gemm1_mma<<<grid, 256, GEMM_SMEM>>>(enc_b, hidden, mbase);
        cudaEventRecord(eG[c], 0);
        cudaStreamWaitEvent(sK, eG[c], 0);
        topk_select<<<CHROWS, NT3, 0, sK>>>(x, enc_w, enc_b, hidden, mbase);
        gemm2_sparse<<<CHROWS, 256, 0, sK>>>(dec_b, hidden, out, mbase);
    }
    cudaEventRecord(eEnd, sK);
    cudaStreamWaitEvent(0, eEnd, 0);
}

// round 17
// speedup vs baseline: 1.0820x; 1.0820x over previous
#include <cuda_runtime.h>
#include <cuda_bf16.h>
#include <cstdint>

#define BATCH   8192
#define IN_DIM  256
#define HID_DIM 16384
#define OUT_DIM 256
#define K_SEL   256
#define LIST_CAP 320
#define BAND_CAP 64
#define CAND_CAP 768
#define NT3      256

// bf16x2 split GEMM (3 terms): K expanded 3x (hi*hi, hi*mid, mid*hi)
#define KTOT  768

// HMMA tile config (round-8 proven: 128x128, warp 64x32, 2 CTA/SM)
#define BM 128
#define BN 128
#define BK 32
#define NSTAGES 4
#define KITERS (KTOT / BK)
#define STAGE_BYTES (2 * BM * BK * 2)
#define GEMM_SMEM (NSTAGES * STAGE_BYTES)

typedef unsigned long long u64;

__device__ float         g_dec_wT[(size_t)HID_DIM * OUT_DIM];
__device__ __nv_bfloat16 g_xs[(size_t)BATCH  * KTOT];
__device__ __nv_bfloat16 g_ws[(size_t)HID_DIM * KTOT];
__device__ int           g_nsel[BATCH];
__device__ int           g_lj[(size_t)BATCH * LIST_CAP];
__device__ float         g_lv[(size_t)BATCH * LIST_CAP];

// ---------------------------------------------------------------------------
// PTX helpers (sm_80-level only; ptxas targets sm_103 with no 'a' features)
// ---------------------------------------------------------------------------
__device__ __forceinline__ uint32_t smem_u32(const void* p) {
    uint32_t a;
    asm("{ .reg .u64 t; cvta.to.shared.u64 t, %1; cvt.u32.u64 %0, t; }" : "=r"(a) : "l"(p));
    return a;
}
__device__ __forceinline__ void cp16(uint32_t dst, const void* src) {
    asm volatile("cp.async.cg.shared.global [%0], [%1], 16;" :: "r"(dst), "l"(src));
}
__device__ __forceinline__ void cp_commit() {
    asm volatile("cp.async.commit_group;" ::: "memory");
}
__device__ __forceinline__ void ldsm4(uint32_t& r0, uint32_t& r1, uint32_t& r2, uint32_t& r3,
                                      uint32_t addr) {
    asm volatile("ldmatrix.sync.aligned.m8n8.x4.shared.b16 {%0,%1,%2,%3}, [%4];"
                 : "=r"(r0), "=r"(r1), "=r"(r2), "=r"(r3) : "r"(addr));
}
__device__ __forceinline__ void mma16816(float* c, const uint32_t* a, const uint32_t* b) {
    asm volatile(
        "mma.sync.aligned.m16n8k16.row.col.f32.bf16.bf16.f32 "
        "{%0,%1,%2,%3}, {%4,%5,%6,%7}, {%8,%9}, {%0,%1,%2,%3};"
        : "+f"(c[0]), "+f"(c[1]), "+f"(c[2]), "+f"(c[3])
        : "r"(a[0]), "r"(a[1]), "r"(a[2]), "r"(a[3]), "r"(b[0]), "r"(b[1]));
}

// ---------------------------------------------------------------------------
// split fp32 -> 2x bf16 along expanded K (3-term product)
// ---------------------------------------------------------------------------
__global__ void split_x(const float* __restrict__ x)
{
    const int i = blockIdx.x * 256 + threadIdx.x;
    const int m = i >> 8, k = i & 255;
    const float v = x[i];
    const __nv_bfloat16 hi = __float2bfloat16(v);
    const float r1 = v - __bfloat162float(hi);
    const __nv_bfloat16 mid = __float2bfloat16(r1);
    __nv_bfloat16* dst = g_xs + (size_t)m * KTOT + k;
    dst[0] = hi; dst[256] = hi; dst[512] = mid;
}
__global__ void split_w(const float* __restrict__ w)
{
    const int i = blockIdx.x * 256 + threadIdx.x;
    const int n = i >> 8, k = i & 255;
    const float v = w[i];
    const __nv_bfloat16 hi = __float2bfloat16(v);
    const float r1 = v - __bfloat162float(hi);
    const __nv_bfloat16 mid = __float2bfloat16(r1);
    __nv_bfloat16* dst = g_ws + (size_t)n * KTOT + k;
    dst[0] = hi; dst[256] = mid; dst[512] = hi;
}

// ---------------------------------------------------------------------------
// HMMA bf16 GEMM:  h = relu(A' B'^T + bias)  (round-8 version, verbatim)
// ---------------------------------------------------------------------------
__device__ __forceinline__ uint32_t sw_off(int row, int gran) {
    return (uint32_t)(row * 64 + ((gran ^ ((row >> 1) & 3)) << 4));
}

__global__ __launch_bounds__(256, 2)
void gemm1_mma(const float* __restrict__ bias, float* __restrict__ h)
{
    extern __shared__ __align__(1024) char smem[];
    const uint32_t sb = smem_u32(smem);
    const int tid = threadIdx.x;
    const int wid = tid >> 5;
    const int lane = tid & 31;
    const int m0 = blockIdx.x * BM;
    const int n0 = blockIdx.y * BN;

    const int warp_m = wid >> 2;
    const int warp_n = wid & 3;

    float acc[4][4][4];
#pragma unroll
    for (int i = 0; i < 4; i++)
#pragma unroll
        for (int j = 0; j < 4; j++)
#pragma unroll
            for (int q = 0; q < 4; q++) acc[i][j][q] = 0.0f;

    const int ar0 = (tid + 0)   >> 2, ag0 = (tid + 0)   & 3;
    const int ar1 = (tid + 256) >> 2, ag1 = (tid + 256) & 3;

    auto issue = [&](int c, int s) {
        const uint32_t abase = sb + s * STAGE_BYTES;
        const uint32_t bbase = abase + BM * BK * 2;
        const __nv_bfloat16* ax = g_xs + (size_t)m0 * KTOT + c * BK;
        const __nv_bfloat16* bx = g_ws + (size_t)n0 * KTOT + c * BK;
        cp16(abase + sw_off(ar0, ag0), ax + (size_t)ar0 * KTOT + ag0 * 8);
        cp16(abase + sw_off(ar1, ag1), ax + (size_t)ar1 * KTOT + ag1 * 8);
        cp16(bbase + sw_off(ar0, ag0), bx + (size_t)ar0 * KTOT + ag0 * 8);
        cp16(bbase + sw_off(ar1, ag1), bx + (size_t)ar1 * KTOT + ag1 * 8);
    };

    issue(0, 0); cp_commit();
    issue(1, 1); cp_commit();
    issue(2, 2); cp_commit();

    const int a_row_in = warp_m * 64 + (lane & 15);
    const int a_gsel   = (lane >> 4);
    const int b_row_in = warp_n * 32 + (lane & 7) + ((lane >> 4) << 3);
    const int b_gsel   = (lane >> 3) & 1;

    for (int c = 0; c < KITERS; c++) {
        asm volatile("cp.async.wait_group 2;" ::: "memory");
        __syncthreads();

        if (c + 3 < KITERS) issue(c + 3, (c + 3) & (NSTAGES - 1));
        cp_commit();

        const uint32_t abase = sb + (c & (NSTAGES - 1)) * STAGE_BYTES;
        const uint32_t bbase = abase + BM * BK * 2;

#pragma unroll
        for (int ks = 0; ks < 2; ks++) {
            uint32_t af[4][4];
            uint32_t bf[4][2];
#pragma unroll
            for (int ti = 0; ti < 4; ti++) {
                const int r = a_row_in + ti * 16;
                ldsm4(af[ti][0], af[ti][1], af[ti][2], af[ti][3],
                      abase + sw_off(r, ks * 2 + a_gsel));
            }
#pragma unroll
            for (int tjj = 0; tjj < 2; tjj++) {
                const int r = b_row_in + tjj * 16;
                uint32_t r0, r1, r2, r3;
                ldsm4(r0, r1, r2, r3, bbase + sw_off(r, ks * 2 + b_gsel));
                bf[tjj * 2 + 0][0] = r0; bf[tjj * 2 + 0][1] = r1;
                bf[tjj * 2 + 1][0] = r2; bf[tjj * 2 + 1][1] = r3;
            }
#pragma unroll
            for (int ti = 0; ti < 4; ti++)
#pragma unroll
                for (int tj = 0; tj < 4; tj++)
                    mma16816(acc[ti][tj], af[ti], bf[tj]);
        }
        __syncthreads();
    }

    __syncthreads();
    float* esm = (float*)smem + wid * (64 * 32);
#pragma unroll
    for (int ti = 0; ti < 4; ti++)
#pragma unroll
        for (int tj = 0; tj < 4; tj++) {
            const int r = ti * 16 + (lane >> 2);
            const int cc = tj * 8 + (lane & 3) * 2;
            esm[r * 32 + cc]            = acc[ti][tj][0];
            esm[r * 32 + cc + 1]        = acc[ti][tj][1];
            esm[(r + 8) * 32 + cc]      = acc[ti][tj][2];
            esm[(r + 8) * 32 + cc + 1]  = acc[ti][tj][3];
        }
    __syncwarp();
    {
        const int col = n0 + warp_n * 32 + lane;
        const float bl = bias[col];
        float* hb = h + (size_t)(m0 + warp_m * 64) * HID_DIM + col;
#pragma unroll 4
        for (int r = 0; r < 64; r++) {
            float v = esm[r * 32 + lane] + bl;
            hb[(size_t)r * HID_DIM] = v > 0.0f ? v : 0.0f;
        }
    }
}

// ---------------------------------------------------------------------------
// transpose dec_w
// ---------------------------------------------------------------------------
__global__ void transpose_dec(const float* __restrict__ dec_w)
{
    __shared__ float tile[32][33];
    const int j0 = blockIdx.x * 32;
    const int o0 = blockIdx.y * 32;
    const int tx = threadIdx.x;
    const int ty = threadIdx.y;
#pragma unroll
    for (int i = 0; i < 4; i++)
        tile[ty + i * 8][tx] = dec_w[(size_t)(o0 + ty + i * 8) * HID_DIM + (j0 + tx)];
    __syncthreads();
#pragma unroll
    for (int i = 0; i < 4; i++)
        g_dec_wT[(size_t)(j0 + ty + i * 8) * OUT_DIM + (o0 + tx)] = tile[tx][ty + i * 8];
}

// ---------------------------------------------------------------------------
// Kernel 3a: selection — byte-identical to the round-8 passing version.
// ---------------------------------------------------------------------------
__global__ __launch_bounds__(NT3)
void topk_select(const float* __restrict__ x,
                 const float* __restrict__ enc_w,
                 const float* __restrict__ enc_b,
                 float* __restrict__ hidden)
{
    __shared__ unsigned hist[2048];
    __shared__ int scanbuf[NT3];
    __shared__ int cand_idx[CAND_CAP];
    __shared__ float cand_val[CAND_CAP];
    __shared__ float cand_out[CAND_CAP];
    __shared__ unsigned char cand_keep[CAND_CAP];
    __shared__ float xrow[IN_DIM];
    __shared__ int band_c[BAND_CAP];
    __shared__ float band_ex[BAND_CAP];
    __shared__ int wsum[8];
    __shared__ int s_pos, s_ccnt, s_bin, s_hidef, s_tbits, s_def, s_hi2, s_bandcnt, s_keepcnt;

    const int tid = threadIdx.x;
    const int lane = tid & 31, warp = tid >> 5;
    const int brow = blockIdx.x;
    float* hrow = hidden + (size_t)brow * HID_DIM;
    float4* hv = (float4*)hrow;

#pragma unroll
    for (int i = tid; i < 2048; i += NT3) hist[i] = 0u;
    xrow[tid] = x[(size_t)brow * IN_DIM + tid];
    if (tid == 0) { s_pos = 0; s_ccnt = 0; s_bin = -1; s_hidef = 0; s_tbits = 0;
                    s_hi2 = 0; s_bandcnt = 0; s_keepcnt = 0; }
    __syncthreads();

    // ---- Pass A: histogram of positive values (bins = u>>20) ----
    {
        int my_pos = 0;
        for (int i = tid; i < HID_DIM / 4; i += NT3) {
            const float4 v = hv[i];
            if (v.x > 0.0f) { my_pos++; atomicAdd(&hist[__float_as_uint(v.x) >> 20], 1u); }
            if (v.y > 0.0f) { my_pos++; atomicAdd(&hist[__float_as_uint(v.y) >> 20], 1u); }
            if (v.z > 0.0f) { my_pos++; atomicAdd(&hist[__float_as_uint(v.z) >> 20], 1u); }
            if (v.w > 0.0f) { my_pos++; atomicAdd(&hist[__float_as_uint(v.w) >> 20], 1u); }
        }
#pragma unroll
        for (int o = 16; o; o >>= 1) my_pos += __shfl_xor_sync(0xffffffffu, my_pos, o);
        if (lane == 0) atomicAdd(&s_pos, my_pos);
    }
    __syncthreads();

    if (s_pos < K_SEL) {
        if (tid == 0) g_nsel[brow] = -1;
        return;
    }

    const int b8 = tid * 8;
    {
        int ts = 0;
#pragma unroll
        for (int q = 0; q < 8; q++) ts += (int)hist[b8 + q];
        scanbuf[tid] = ts;
        __syncthreads();
        for (int off = 1; off < NT3; off <<= 1) {
            const int add = (tid + off < NT3) ? scanbuf[tid + off] : 0;
            __syncthreads();
            scanbuf[tid] += add;
            __syncthreads();
        }
        int running = (tid < NT3 - 1) ? scanbuf[tid + 1] : 0;
        for (int bb = b8 + 7; bb >= b8; bb--) {
            const int c = (int)hist[bb];
            if (running < K_SEL && running + c >= K_SEL) s_bin = bb;
            running += c;
        }
    }
    __syncthreads();
    const int b = s_bin;
    if (b <= 8) {
        if (tid == 0) g_nsel[brow] = -1;
        return;
    }
    {
        int part = 0;
#pragma unroll
        for (int q = 0; q < 8; q++) { const int bb = b8 + q; if (bb >= b + 2) part += (int)hist[bb]; }
#pragma unroll
        for (int o = 16; o; o >>= 1) part += __shfl_xor_sync(0xffffffffu, part, o);
        if (lane == 0) atomicAdd(&s_hidef, part);
    }
    __syncthreads();

    // ---- Pass B: write post (definite/zero) in place, collect candidates ----
    int cnt = 0;
    for (int i = tid; i < HID_DIM / 4; i += NT3) {
        float4 v = hv[i];
        float4 o;
        {
            const int ub = (int)(__float_as_uint(v.x) >> 20);
            if (v.x > 0.0f && ub >= b + 2) { o.x = v.x; cnt++; }
            else { o.x = 0.0f; if (v.x > 0.0f && ub >= b - 1 && ub <= b + 1) {
                const int p = atomicAdd(&s_ccnt, 1);
                if (p < CAND_CAP) { cand_idx[p] = i * 4 + 0; cand_val[p] = v.x; } } }
        }
        {
            const int ub = (int)(__float_as_uint(v.y) >> 20);
            if (v.y > 0.0f && ub >= b + 2) { o.y = v.y; cnt++; }
            else { o.y = 0.0f; if (v.y > 0.0f && ub >= b - 1 && ub <= b + 1) {
                const int p = atomicAdd(&s_ccnt, 1);
                if (p < CAND_CAP) { cand_idx[p] = i * 4 + 1; cand_val[p] = v.y; } } }
        }
        {
            const int ub = (int)(__float_as_uint(v.z) >> 20);
            if (v.z > 0.0f && ub >= b + 2) { o.z = v.z; cnt++; }
            else { o.z = 0.0f; if (v.z > 0.0f && ub >= b - 1 && ub <= b + 1) {
                const int p = atomicAdd(&s_ccnt, 1);
                if (p < CAND_CAP) { cand_idx[p] = i * 4 + 2; cand_val[p] = v.z; } } }
        }
        {
            const int ub = (int)(__float_as_uint(v.w) >> 20);
            if (v.w > 0.0f && ub >= b + 2) { o.w = v.w; cnt++; }
            else { o.w = 0.0f; if (v.w > 0.0f && ub >= b - 1 && ub <= b + 1) {
                const int p = atomicAdd(&s_ccnt, 1);
                if (p < CAND_CAP) { cand_idx[p] = i * 4 + 3; cand_val[p] = v.w; } } }
        }
        hv[i] = o;
    }
    __syncthreads();

    // ---- scan definite counts -> deterministic list bases ----
    int incl = cnt;
#pragma unroll
    for (int o = 1; o < 32; o <<= 1) {
        const int n = __shfl_up_sync(0xffffffffu, incl, o);
        if (lane >= o) incl += n;
    }
    if (lane == 31) wsum[warp] = incl;
    __syncthreads();
    if (warp == 0 && lane < 8) {
        int v = wsum[lane];
        int s = v;
#pragma unroll
        for (int o = 1; o < 8; o <<= 1) {
            const int n = __shfl_up_sync(0x000000ffu, s, o);
            if (lane >= o) s += n;
        }
        wsum[lane] = s - v;
        if (lane == 7) s_def = s;
    }
    __syncthreads();
    int base = wsum[warp] + (incl - cnt);

    for (int i = tid; i < HID_DIM / 4; i += NT3) {
        const float4 v = hv[i];
        if (v.x != 0.0f) {
            if (base < LIST_CAP) { g_lj[(size_t)brow * LIST_CAP + base] = i * 4 + 0;
                                   g_lv[(size_t)brow * LIST_CAP + base] = v.x; }
            base++;
        }
        if (v.y != 0.0f) {
            if (base < LIST_CAP) { g_lj[(size_t)brow * LIST_CAP + base] = i * 4 + 1;
                                   g_lv[(size_t)brow * LIST_CAP + base] = v.y; }
            base++;
        }
        if (v.z != 0.0f) {
            if (base < LIST_CAP) { g_lj[(size_t)brow * LIST_CAP + base] = i * 4 + 2;
                                   g_lv[(size_t)brow * LIST_CAP + base] = v.z; }
            base++;
        }
        if (v.w != 0.0f) {
            if (base < LIST_CAP) { g_lj[(size_t)brow * LIST_CAP + base] = i * 4 + 3;
                                   g_lv[(size_t)brow * LIST_CAP + base] = v.w; }
            base++;
        }
    }

    // ---- exact threshold among candidates ----
    const int C = (s_ccnt < CAND_CAP) ? s_ccnt : CAND_CAP;
    const int k_rem = K_SEL - s_hidef;
    for (int c = tid; c < C; c += NT3) {
        const float mine = cand_val[c];
        int gt = 0, eq = 0;
        for (int j = 0; j < C; j++) {
            const float o = cand_val[j];
            gt += (o > mine); eq += (o == mine);
        }
        if (gt < k_rem && gt + eq >= k_rem) s_tbits = __float_as_int(mine);
    }
    __syncthreads();
    const float t = __int_as_float(s_tbits);
    const float eps = 3e-3f;

    for (int c = tid; c < C; c += NT3) {
        const float v = cand_val[c];
        if (v > t + eps) { cand_keep[c] = 1; cand_out[c] = v; atomicAdd(&s_hi2, 1); }
        else if (v >= t - eps) {
            cand_keep[c] = 0;
            const int p = atomicAdd(&s_bandcnt, 1);
            if (p < BAND_CAP) band_c[p] = c;
        } else cand_keep[c] = 0;
    }
    __syncthreads();
    const int bc = (s_bandcnt < BAND_CAP) ? s_bandcnt : BAND_CAP;
    const int k_remb = k_rem - s_hi2;
    if (tid < bc) {
        const int j = cand_idx[band_c[tid]];
        const float4* wj = (const float4*)(enc_w + (size_t)j * IN_DIM);
        float acc = 0.0f;
#pragma unroll 8
        for (int k4 = 0; k4 < IN_DIM / 4; k4++) {
            const float4 wv = __ldg(&wj[k4]);
            acc = fmaf(xrow[k4 * 4 + 0], wv.x, acc);
            acc = fmaf(xrow[k4 * 4 + 1], wv.y, acc);
            acc = fmaf(xrow[k4 * 4 + 2], wv.z, acc);
            acc = fmaf(xrow[k4 * 4 + 3], wv.w, acc);
        }
        acc += enc_b[j];
        band_ex[tid] = acc > 0.0f ? acc : 0.0f;
    }
    __syncthreads();
    if (tid < bc) {
        const float mine = band_ex[tid];
        int gt = 0;
        for (int q = 0; q < bc; q++) gt += (band_ex[q] > mine);
        if (gt < k_remb) {
            const int c = band_c[tid];
            cand_keep[c] = 1;
            cand_out[c] = band_ex[tid];
        }
    }
    __syncthreads();

    for (int c = tid; c < C; c += NT3) {
        if (cand_keep[c]) {
            const int myidx = cand_idx[c];
            int pos = 0;
            for (int j = 0; j < C; j++)
                pos += (cand_keep[j] && cand_idx[j] < myidx);
            const int slot = s_def + pos;
            if (slot < LIST_CAP) {
                g_lj[(size_t)brow * LIST_CAP + slot] = myidx;
                g_lv[(size_t)brow * LIST_CAP + slot] = cand_out[c];
            }
            hrow[myidx] = cand_out[c];
            atomicAdd(&s_keepcnt, 1);
        }
    }
    __syncthreads();
    if (tid == 0) {
        int n = s_def + s_keepcnt;
        g_nsel[brow] = (n < LIST_CAP) ? n : LIST_CAP;
    }
}

// ---------------------------------------------------------------------------
// Kernel 3b: sparse decode GEMM — column-pair float2 loads, list split into
// two halves (128 col-pairs x 2 halves = 256 threads). ~1.7x fewer
// instructions per output element than the scalar version.
// ---------------------------------------------------------------------------
__global__ __launch_bounds__(256)
void gemm2_sparse(const float* __restrict__ dec_b,
                  const float* __restrict__ hidden,
                  float* __restrict__ out)
{
    __shared__ int lj[LIST_CAP];
    __shared__ float lv[LIST_CAP];
    __shared__ float part[2][OUT_DIM];
    const int tid = threadIdx.x;
    const int brow = blockIdx.x;
    const int nsel = g_nsel[brow];
    const int half = tid >> 7;            // 0/1: which half of the list
    const int cp   = (tid & 127) * 2;     // column pair base

    float a0 = 0.0f, a1 = 0.0f;
    if (nsel >= 0) {
        for (int i = tid; i < nsel; i += 256) {
            lj[i] = g_lj[(size_t)brow * LIST_CAP + i];
            lv[i] = g_lv[(size_t)brow * LIST_CAP + i];
        }
        __syncthreads();
        const int h1 = nsel >> 1;
        const int s0 = half ? h1 : 0;
        const int s1 = half ? nsel : h1;
        int s = s0;
        for (; s + 4 <= s1; s += 4) {
#pragma unroll
            for (int q = 0; q < 4; q++) {
                const float vv = lv[s + q];
                const float2 w = *(const float2*)&g_dec_wT[(size_t)lj[s + q] * OUT_DIM + cp];
                a0 = fmaf(vv, w.x, a0);
                a1 = fmaf(vv, w.y, a1);
            }
        }
        for (; s < s1; s++) {
            const float vv = lv[s];
            const float2 w = *(const float2*)&g_dec_wT[(size_t)lj[s] * OUT_DIM + cp];
            a0 = fmaf(vv, w.x, a0);
            a1 = fmaf(vv, w.y, a1);
        }
    } else {
        const float* hrow = hidden + (size_t)brow * HID_DIM;
        const int j0 = half * (HID_DIM / 2);
        for (int j = j0; j < j0 + HID_DIM / 2; j++) {
            const float vv = __ldg(&hrow[j]);
            const float2 w = *(const float2*)&g_dec_wT[(size_t)j * OUT_DIM + cp];
            a0 = fmaf(vv, w.x, a0);
            a1 = fmaf(vv, w.y, a1);
        }
        __syncthreads();
    }
    part[half][cp]     = a0;
    part[half][cp + 1] = a1;
    __syncthreads();
    out[(size_t)brow * OUT_DIM + tid] = dec_b[tid] + part[0][tid] + part[1][tid];
}

// ---------------------------------------------------------------------------
// Launch (round-8 single-stream topology)
// ---------------------------------------------------------------------------
extern "C" void kernel_launch(void* const* d_in, const int* in_sizes, int n_in,
                              void* d_out, int out_size)
{
    const float* x     = (const float*)d_in[0];
    const float* enc_w = (const float*)d_in[1];
    const float* enc_b = (const float*)d_in[2];
    const float* dec_w = (const float*)d_in[3];
    const float* dec_b = (const float*)d_in[4];

    float* out    = (float*)d_out;
    float* hidden = (float*)d_out + (size_t)BATCH * OUT_DIM;

    cudaFuncSetAttribute(gemm1_mma,
                         cudaFuncAttributeMaxDynamicSharedMemorySize,
                         GEMM_SMEM);

    {
        dim3 grid(HID_DIM / 32, OUT_DIM / 32);
        dim3 block(32, 8);
        transpose_dec<<<grid, block>>>(dec_w);
    }
    split_x<<<(BATCH * IN_DIM) / 256, 256>>>(x);
    split_w<<<((size_t)HID_DIM * IN_DIM) / 256, 256>>>(enc_w);

    {
        dim3 grid(BATCH / BM, HID_DIM / BN);
        gemm1_mma<<<grid, 256, GEMM_SMEM>>>(enc_b, hidden);
    }
    topk_select<<<BATCH, NT3>>>(x, enc_w, enc_b, hidden);
    gemm2_sparse<<<BATCH, 256>>>(dec_b, hidden, out);
}